// round 12
// baseline (speedup 1.0000x reference)
#include <cuda_runtime.h>
#include <stdint.h>

// ---------------------------------------------------------------------------
// GNN_Layer_Init: out[N,32] = segment_sum_e( edge_val[e] * weight[edge_col[e],:],
//                                            seg=edge_row[e] ) + bias
// N = 100000, D = 32, E = 1.6M
//
// Inputs (metadata order):
//   d_in[0] edge_row  int32 [E]
//   d_in[1] edge_col  int32 [E]
//   d_in[2] edge_val  fp32  [E]
//   d_in[3] weight    fp32  [N,32]
//   d_in[4] bias      fp32  [32]
// Output: fp32 [N,32]
//
// R10: R6 structure (8 lanes/edge, 4 edges/thread, int4 scalar broadcast),
// but every gather LDG.128 and scatter RED.v4 is split into 4 PREDICATED
// single-edge instructions (one group active per instruction). Each memory
// instruction then touches exactly ONE 128B line -> 1 L1TEX wavefront,
// no within-instruction replays (2.07 cyc/wf -> 1.0 cyc/wf).
// Extra issue slots land on the idle issue pipe (13.9%).
// ---------------------------------------------------------------------------

#define D 32
#define DV 8  // float4 chunks per row

__global__ void init_out_kernel(float4* __restrict__ out,
                                const float* __restrict__ bias,
                                int n_vec)  // n_vec = N * DV
{
    int t = blockIdx.x * blockDim.x + threadIdx.x;
    if (t >= n_vec) return;
    const float4* b4 = reinterpret_cast<const float4*>(bias);
    out[t] = b4[t & (DV - 1)];
}

// Predicated L2-only v4 gather: executes (and generates a wavefront) only on
// lanes where is_active != 0. Inactive lanes keep r = 0.
__device__ __forceinline__ float4 ldg_cg_v4_pred(const float4* p, int is_active)
{
    float4 r = make_float4(0.f, 0.f, 0.f, 0.f);
    asm volatile("{\n\t"
                 ".reg .pred q;\n\t"
                 "setp.ne.s32 q, %5, 0;\n\t"
                 "@q ld.global.cg.v4.f32 {%0, %1, %2, %3}, [%4];\n\t"
                 "}"
                 : "+f"(r.x), "+f"(r.y), "+f"(r.z), "+f"(r.w)
                 : "l"(p), "r"(is_active));
    return r;
}

// Predicated vector reduction: one 128B line per instruction.
__device__ __forceinline__ void red_add_v4_pred(float* addr, float4 v, int is_active)
{
    asm volatile("{\n\t"
                 ".reg .pred q;\n\t"
                 "setp.ne.s32 q, %6, 0;\n\t"
                 "@q red.global.add.v4.f32 [%0], {%1, %2, %3, %4};\n\t"
                 "}"
                 :: "l"(addr), "f"(v.x), "f"(v.y), "f"(v.z), "f"(v.w),
                    "r"(is_active), "r"(is_active)
                 : "memory");
}

__device__ __forceinline__ int4 ldg_cs_i4(const int4* p)
{
    int4 r;
    asm volatile("ld.global.cs.v4.b32 {%0, %1, %2, %3}, [%4];"
                 : "=r"(r.x), "=r"(r.y), "=r"(r.z), "=r"(r.w) : "l"(p));
    return r;
}

__device__ __forceinline__ float4 ldg_cs_f4(const float4* p)
{
    float4 r;
    asm volatile("ld.global.cs.v4.f32 {%0, %1, %2, %3}, [%4];"
                 : "=f"(r.x), "=f"(r.y), "=f"(r.z), "=f"(r.w) : "l"(p));
    return r;
}

__global__ __launch_bounds__(256)
void spmm_edge_pred_kernel(const int4* __restrict__ edge_row4,
                           const int4* __restrict__ edge_col4,
                           const float4* __restrict__ edge_val4,
                           const float* __restrict__ weight,
                           float* __restrict__ out,
                           int n_groups)   // E / 4
{
    int tid = blockIdx.x * blockDim.x + threadIdx.x;
    int g = tid >> 3;        // edge-group index (4 edges per group)
    int j = tid & 7;         // float4 chunk within the 32-float row
    if (g >= n_groups) return;

    int grp = g & 3;         // which of the 4 groups within this warp

    // Per-group predicates, computed once (ISETP x4).
    int a0 = (grp == 0);
    int a1 = (grp == 1);
    int a2 = (grp == 2);
    int a3 = (grp == 3);

    // 8 lanes read the same 16B -> single broadcast wavefront per array.
    int4   r4 = ldg_cs_i4(edge_row4 + g);
    int4   c4 = ldg_cs_i4(edge_col4 + g);
    float4 v4 = ldg_cs_f4(edge_val4 + g);

    const float4* w4 = reinterpret_cast<const float4*>(weight);

    int   rr[4] = {r4.x, r4.y, r4.z, r4.w};
    int   cc[4] = {c4.x, c4.y, c4.z, c4.w};
    float vv[4] = {v4.x, v4.y, v4.z, v4.w};

    // Gather: 16 predicated LDG.128, each with 8 active lanes on 1 line.
    // All 16 issue back-to-back -> MLP is preserved.
    float4 w[4];
#pragma unroll
    for (int k = 0; k < 4; k++) {
        const float4* p = w4 + (size_t)cc[k] * DV + j;
        float4 t0 = ldg_cg_v4_pred(p, a0);
        float4 t1 = ldg_cg_v4_pred(p, a1);
        float4 t2 = ldg_cg_v4_pred(p, a2);
        float4 t3 = ldg_cg_v4_pred(p, a3);
        // Exactly one of t0..t3 is live per lane; sum selects it (FADD, cheap
        // on the 1.7%-busy fma pipe, avoids SELs).
        w[k].x = t0.x + t1.x + t2.x + t3.x;
        w[k].y = t0.y + t1.y + t2.y + t3.y;
        w[k].z = t0.z + t1.z + t2.z + t3.z;
        w[k].w = t0.w + t1.w + t2.w + t3.w;
    }

    // Scatter: 16 predicated RED.v4, each with 8 active lanes on 1 line.
#pragma unroll
    for (int k = 0; k < 4; k++) {
        float4 p;
        p.x = vv[k] * w[k].x;
        p.y = vv[k] * w[k].y;
        p.z = vv[k] * w[k].z;
        p.w = vv[k] * w[k].w;
        float* oaddr = out + (size_t)rr[k] * D + j * 4;
        red_add_v4_pred(oaddr, p, a0);
        red_add_v4_pred(oaddr, p, a1);
        red_add_v4_pred(oaddr, p, a2);
        red_add_v4_pred(oaddr, p, a3);
    }
}

extern "C" void kernel_launch(void* const* d_in, const int* in_sizes, int n_in,
                              void* d_out, int out_size)
{
    const int*   edge_row = (const int*)d_in[0];
    const int*   edge_col = (const int*)d_in[1];
    const float* edge_val = (const float*)d_in[2];
    const float* weight   = (const float*)d_in[3];
    const float* bias     = (const float*)d_in[4];
    float*       out      = (float*)d_out;

    int E = in_sizes[0];
    int n_vec = out_size / 4;  // number of float4 elements in out

    {
        int threads = 256;
        int blocks = (n_vec + threads - 1) / threads;
        init_out_kernel<<<blocks, threads>>>((float4*)out, bias, n_vec);
    }
    {
        int n_groups = E >> 2;  // E divisible by 4 (1.6M)
        int threads = 256;
        long long total = (long long)n_groups * 8;
        int blocks = (int)((total + threads - 1) / threads);
        spmm_edge_pred_kernel<<<blocks, threads>>>(
            (const int4*)edge_row, (const int4*)edge_col,
            (const float4*)edge_val, weight, out, n_groups);
    }
}

// round 17
// speedup vs baseline: 1.1883x; 1.1883x over previous
#include <cuda_runtime.h>
#include <cuda_fp16.h>
#include <stdint.h>

// ---------------------------------------------------------------------------
// GNN_Layer_Init: out[N,32] = segment_sum_e( edge_val[e] * weight[edge_col[e],:],
//                                            seg=edge_row[e] ) + bias
// N = 100000, D = 32, E = 1.6M
//
// Inputs (metadata order):
//   d_in[0] edge_row  int32 [E]
//   d_in[1] edge_col  int32 [E]
//   d_in[2] edge_val  fp32  [E]
//   d_in[3] weight    fp32  [N,32]
//   d_in[4] bias      fp32  [32]
// Output: fp32 [N,32]
//
// R13: R9 coop4 structure (8 lanes/edge, 4 edges/thread, vectorized scalar
// broadcast) + fp16 weight gather:
//   - weight converted once per call to __half in __device__ scratch (6.4MB)
//   - gather is LDG.64 (uint2 = 4 halfs) per lane -> 64B/edge instead of 128B
//   - products and RED scatter remain fp32 (precision: weight quantization
//     only, ~1.4e-4 rms << 1e-3 gate)
// L1 busy time proved invariant to access reorganization (R6/R9/R12 all
// ~31us) -> cut bytes instead.
// ---------------------------------------------------------------------------

#define NN 100000
#define D 32
#define DV 8  // float4 chunks per fp32 out row

// fp16 weight scratch: N*D halfs = 6.4MB
__device__ __align__(16) __half g_wh[NN * D];

__global__ void convert_weight_kernel(const float4* __restrict__ w4, int n4)
{
    int t = blockIdx.x * blockDim.x + threadIdx.x;
    if (t >= n4) return;
    float4 f = __ldg(w4 + t);
    union { uint2 u; __half2 h[2]; } pk;
    pk.h[0] = __floats2half2_rn(f.x, f.y);
    pk.h[1] = __floats2half2_rn(f.z, f.w);
    reinterpret_cast<uint2*>(g_wh)[t] = pk.u;
}

__global__ void init_out_kernel(float4* __restrict__ out,
                                const float* __restrict__ bias,
                                int n_vec)  // n_vec = N * DV
{
    int t = blockIdx.x * blockDim.x + threadIdx.x;
    if (t >= n_vec) return;
    const float4* b4 = reinterpret_cast<const float4*>(bias);
    out[t] = b4[t & (DV - 1)];
}

__device__ __forceinline__ void red_add_v4(float* addr, float4 v)
{
    asm volatile("red.global.add.v4.f32 [%0], {%1, %2, %3, %4};"
                 :: "l"(addr), "f"(v.x), "f"(v.y), "f"(v.z), "f"(v.w)
                 : "memory");
}

__device__ __forceinline__ uint2 ldg_cg_v2(const uint2* p)
{
    uint2 r;
    asm volatile("ld.global.cg.v2.b32 {%0, %1}, [%2];"
                 : "=r"(r.x), "=r"(r.y) : "l"(p));
    return r;
}

__device__ __forceinline__ int4 ldg_cs_i4(const int4* p)
{
    int4 r;
    asm volatile("ld.global.cs.v4.b32 {%0, %1, %2, %3}, [%4];"
                 : "=r"(r.x), "=r"(r.y), "=r"(r.z), "=r"(r.w) : "l"(p));
    return r;
}

__device__ __forceinline__ float4 ldg_cs_f4(const float4* p)
{
    float4 r;
    asm volatile("ld.global.cs.v4.f32 {%0, %1, %2, %3}, [%4];"
                 : "=f"(r.x), "=f"(r.y), "=f"(r.z), "=f"(r.w) : "l"(p));
    return r;
}

__global__ __launch_bounds__(256)
void spmm_edge_h_kernel(const int4* __restrict__ edge_row4,
                        const int4* __restrict__ edge_col4,
                        const float4* __restrict__ edge_val4,
                        float* __restrict__ out,
                        int n_groups)   // E / 4
{
    int tid = blockIdx.x * blockDim.x + threadIdx.x;
    int g = tid >> 3;        // edge-group index (4 edges)
    int j = tid & 7;         // 4-half chunk within the 32-half row
    if (g >= n_groups) return;

    // 8 lanes read the same 16B -> broadcast wavefront per array.
    int4   r4 = ldg_cs_i4(edge_row4 + g);
    int4   c4 = ldg_cs_i4(edge_col4 + g);
    float4 v4 = ldg_cs_f4(edge_val4 + g);

    const uint2* wh = reinterpret_cast<const uint2*>(g_wh);  // row stride: 8 uint2

    int   rr[4] = {r4.x, r4.y, r4.z, r4.w};
    int   cc[4] = {c4.x, c4.y, c4.z, c4.w};
    float vv[4] = {v4.x, v4.y, v4.z, v4.w};

    // 4 independent LDG.64 gathers (64B/edge across the 8-lane group).
    uint2 wraw[4];
#pragma unroll
    for (int k = 0; k < 4; k++)
        wraw[k] = ldg_cg_v2(wh + (size_t)cc[k] * DV + j);

#pragma unroll
    for (int k = 0; k < 4; k++) {
        union { uint2 u; __half2 h[2]; } pk;
        pk.u = wraw[k];
        float2 f0 = __half22float2(pk.h[0]);
        float2 f1 = __half22float2(pk.h[1]);
        float4 p;
        p.x = vv[k] * f0.x;
        p.y = vv[k] * f0.y;
        p.z = vv[k] * f1.x;
        p.w = vv[k] * f1.y;
        red_add_v4(out + (size_t)rr[k] * D + j * 4, p);
    }
}

extern "C" void kernel_launch(void* const* d_in, const int* in_sizes, int n_in,
                              void* d_out, int out_size)
{
    const int*   edge_row = (const int*)d_in[0];
    const int*   edge_col = (const int*)d_in[1];
    const float* edge_val = (const float*)d_in[2];
    const float* weight   = (const float*)d_in[3];
    const float* bias     = (const float*)d_in[4];
    float*       out      = (float*)d_out;

    int E = in_sizes[0];
    int n_vec = out_size / 4;   // float4 elements in out
    int n_w4  = NN * D / 4;     // float4 elements in weight

    {
        int threads = 256;
        convert_weight_kernel<<<(n_w4 + threads - 1) / threads, threads>>>(
            (const float4*)weight, n_w4);
    }
    {
        int threads = 256;
        init_out_kernel<<<(n_vec + threads - 1) / threads, threads>>>(
            (float4*)out, bias, n_vec);
    }
    {
        int n_groups = E >> 2;  // E divisible by 4 (1.6M)
        int threads = 256;
        long long total = (long long)n_groups * 8;
        int blocks = (int)((total + threads - 1) / threads);
        spmm_edge_h_kernel<<<blocks, threads>>>(
            (const int4*)edge_row, (const int4*)edge_col,
            (const float4*)edge_val, out, n_groups);
    }
}